// round 7
// baseline (speedup 1.0000x reference)
#include <cuda_runtime.h>
#include <cuda_bf16.h>
#include <stdint.h>

#define HW 16384
#define NPIX 1048576
#define QPAD 72

// ---------------- scratch (static device allocations) ----------------
__device__ float g_part[2048];
__device__ float g_stats[2];                 // mean
__device__ float g_csum[64];                 // colsum(wqk)
__device__ __nv_bfloat16 g_Q[4 * 4096 * 64]; // unit-norm q * (1/sqrt(8)) (bf16)
__device__ __nv_bfloat16 g_V[4 * 4096 * 64]; // raw v (bf16)
__device__ float g_Po[2 * 16384 * 64];       // split-K partial attn out
__device__ float g_Pd[2 * 16384];            // split-K partial denominators
__device__ float g_T[64 * HW];               // x + convl(...)
__device__ float g_Z1[64 * HW];
__device__ float g_Z2[64 * HW];
__device__ float g_Wt[2][64 * 9 * 64];       // transposed conv weights [(cin*9+kk)*64+co]

// ---------------- f32x2 / misc helpers ----------------
__device__ __forceinline__ unsigned long long dupf(float v) {
    unsigned long long r;
    uint32_t b = __float_as_uint(v);
    asm("mov.b64 %0, {%1,%1};" : "=l"(r) : "r"(b));
    return r;
}
__device__ __forceinline__ void unpackf(unsigned long long v, float& lo, float& hi) {
    uint32_t a, b;
    asm("mov.b64 {%0,%1}, %2;" : "=r"(a), "=r"(b) : "l"(v));
    lo = __uint_as_float(a);
    hi = __uint_as_float(b);
}
__device__ __forceinline__ void fma2(unsigned long long& d, unsigned long long a,
                                     unsigned long long b) {
    asm("fma.rn.f32x2 %0, %1, %2, %0;" : "+l"(d) : "l"(a), "l"(b));
}
__device__ __forceinline__ uint32_t packbf(float lo, float hi) {
    uint32_t r;
    asm("cvt.rn.bf16x2.f32 %0, %1, %2;" : "=r"(r) : "f"(hi), "f"(lo));
    return r;
}
__device__ __forceinline__ uint32_t sptr(const void* p) {
    return (uint32_t)__cvta_generic_to_shared(p);
}
__device__ __forceinline__ void cp16(uint32_t dst, const void* src) {
    asm volatile("cp.async.cg.shared.global [%0], [%1], 16;" :: "r"(dst), "l"(src));
}
__device__ __forceinline__ void cp_commit() {
    asm volatile("cp.async.commit_group;");
}
__device__ __forceinline__ void ldsm_x4(uint32_t a, uint32_t& r0, uint32_t& r1,
                                        uint32_t& r2, uint32_t& r3) {
    asm volatile("ldmatrix.sync.aligned.m8n8.x4.shared.b16 {%0,%1,%2,%3},[%4];"
                 : "=r"(r0), "=r"(r1), "=r"(r2), "=r"(r3) : "r"(a));
}
__device__ __forceinline__ void ldsm_x4t(uint32_t a, uint32_t& r0, uint32_t& r1,
                                         uint32_t& r2, uint32_t& r3) {
    asm volatile("ldmatrix.sync.aligned.m8n8.x4.trans.shared.b16 {%0,%1,%2,%3},[%4];"
                 : "=r"(r0), "=r"(r1), "=r"(r2), "=r"(r3) : "r"(a));
}
__device__ __forceinline__ void ldsm_x2(uint32_t a, uint32_t& r0, uint32_t& r1) {
    asm volatile("ldmatrix.sync.aligned.m8n8.x2.shared.b16 {%0,%1},[%2];"
                 : "=r"(r0), "=r"(r1) : "r"(a));
}
__device__ __forceinline__ void mma_bf16(float* d, const uint32_t* a, const uint32_t* b) {
    asm volatile(
        "mma.sync.aligned.m16n8k16.row.col.f32.bf16.bf16.f32 "
        "{%0,%1,%2,%3},{%4,%5,%6,%7},{%8,%9},{%0,%1,%2,%3};"
        : "+f"(d[0]), "+f"(d[1]), "+f"(d[2]), "+f"(d[3])
        : "r"(a[0]), "r"(a[1]), "r"(a[2]), "r"(a[3]), "r"(b[0]), "r"(b[1]));
}
// exp(d), |d| <= ~0.13 (deg-4 Taylor)
__device__ __forceinline__ float expp(float d) {
    return fmaf(d, fmaf(d, fmaf(d, fmaf(d, 0.041666668f, 0.16666667f), 0.5f), 1.f), 1.f);
}

// ---------------- stage 1: mean over all of x ----------------
__global__ void k_red1(const float4* __restrict__ x4) {
    int i = blockIdx.x * 256 + threadIdx.x;
    float4 v = x4[i];
    float s = v.x + v.y + v.z + v.w;
    for (int o = 16; o; o >>= 1) s += __shfl_xor_sync(0xffffffffu, s, o);
    __shared__ float sh[8];
    int w = threadIdx.x >> 5, l = threadIdx.x & 31;
    if (l == 0) sh[w] = s;
    __syncthreads();
    if (threadIdx.x == 0) {
        float S = 0;
        for (int k = 0; k < 8; k++) S += sh[k];
        g_part[blockIdx.x] = S;
    }
}

__global__ void k_red2(const float* __restrict__ wqk) {
    int tid = threadIdx.x; // 1024 threads
    // colsum(wqk) once for the whole grid (threads 0..63)
    if (tid < 64) {
        float s = 0.f;
#pragma unroll
        for (int c = 0; c < 64; c++) s += wqk[c * 64 + tid];
        g_csum[tid] = s;
    }
    float s = g_part[tid];
    for (int o = 16; o; o >>= 1) s += __shfl_xor_sync(0xffffffffu, s, o);
    __shared__ float sh[32];
    int w = tid >> 5, l = tid & 31;
    if (l == 0) sh[w] = s;
    __syncthreads();
    if (tid == 0) {
        float S = 0;
        for (int k = 0; k < 32; k++) S += sh[k];
        g_stats[0] = S / (float)NPIX;
    }
}

// ---------------- weight transpose for conv smem coalescing ----------------
__global__ void k_wprep(const float* __restrict__ w1, const float* __restrict__ w2) {
    int i = blockIdx.x * 256 + threadIdx.x; // 36864 per conv
    const float* src = blockIdx.y ? w2 : w1;
    int co = i & 63, r = i >> 6;
    int krkc = r % 9, cin = r / 9;
    g_Wt[blockIdx.y][i] = src[(co * 64 + cin) * 9 + krkc];
}

// ---------------- stage 2: build Q (tensor-core) and V ----------------
// q_row = normalize( x_row @ W  -  mean * colsum(W) ) * (1/sqrt 8)
__global__ __launch_bounds__(128) void k_build(const float* __restrict__ x,
                                               const float* __restrict__ wqk) {
    __shared__ __nv_bfloat16 sW[64 * QPAD]; // W^T: sW[e][c]
    __shared__ __nv_bfloat16 sX[64 * QPAD]; // sX[i][c]
    __shared__ float scs[64];
    int tid = threadIdx.x, lane = tid & 31, wid = tid >> 5;
    int r0 = blockIdx.x * 64;
    int b2 = r0 >> 12;
    int hrow = (((r0 & 4095) >> 6) << 1) + (b2 >> 1);
    int wofs = b2 & 1;
    const float* xb = x + hrow * 128 + wofs;

    for (int idx = tid; idx < 4096; idx += 128) {
        int c = idx >> 6, e = idx & 63;
        sW[e * QPAD + c] = __float2bfloat16(wqk[idx]);
    }
    for (int idx = tid; idx < 4096; idx += 128) {
        int c = idx >> 6, i = idx & 63;
        sX[i * QPAD + c] = __float2bfloat16(xb[c * HW + 2 * i]);
    }
    if (tid < 64) scs[tid] = g_csum[tid];
    __syncthreads();

    // write V (raw bf16 x)
    for (int i2 = tid; i2 < 512; i2 += 128) {
        int i = i2 >> 3, c16 = i2 & 7;
        *(uint4*)(g_V + (r0 + i) * 64 + c16 * 8) = *(const uint4*)(sX + i * QPAD + c16 * 8);
    }

    int R0 = wid * 16;
    uint32_t aX[4][4];
    {
        int qrow = R0 + (lane & 7) + ((lane >> 3) & 1) * 8;
        int qcol = ((lane >> 4) & 1) * 8;
#pragma unroll
        for (int s = 0; s < 4; s++) {
            uint32_t a = sptr(sX + qrow * QPAD + s * 16 + qcol);
            ldsm_x4(a, aX[s][0], aX[s][1], aX[s][2], aX[s][3]);
        }
    }
    uint32_t offB = sptr(sW) + ((lane & 7) * QPAD + ((lane >> 3) & 1) * 8) * 2;

    float c[8][4];
#pragma unroll
    for (int j = 0; j < 8; j++)
#pragma unroll
        for (int t = 0; t < 4; t++) c[j][t] = 0.f;
#pragma unroll
    for (int j = 0; j < 8; j++)
#pragma unroll
        for (int s = 0; s < 4; s++) {
            uint32_t b[2];
            ldsm_x2(offB + (uint32_t)(j * 8 * QPAD + s * 16) * 2, b[0], b[1]);
            mma_bf16(c[j], aX[s], b);
        }

    float nmean = -g_stats[0];
    int g = lane >> 2, tq = lane & 3;
    float ssA = 0.f, ssB = 0.f;
#pragma unroll
    for (int j = 0; j < 8; j++) {
        float b0 = nmean * scs[j * 8 + tq * 2];
        float b1 = nmean * scs[j * 8 + tq * 2 + 1];
        c[j][0] += b0; c[j][1] += b1; c[j][2] += b0; c[j][3] += b1;
        ssA += c[j][0] * c[j][0] + c[j][1] * c[j][1];
        ssB += c[j][2] * c[j][2] + c[j][3] * c[j][3];
    }
    ssA += __shfl_xor_sync(0xffffffffu, ssA, 1);
    ssA += __shfl_xor_sync(0xffffffffu, ssA, 2);
    ssB += __shfl_xor_sync(0xffffffffu, ssB, 1);
    ssB += __shfl_xor_sync(0xffffffffu, ssB, 2);
    const float S8 = 0.35355339059327373f; // 1/sqrt(8)
    float invA = S8 / (sqrtf(ssA) + 1e-8f);
    float invB = S8 / (sqrtf(ssB) + 1e-8f);

    int rA = r0 + R0 + g;
#pragma unroll
    for (int j = 0; j < 8; j++) {
        int col = j * 8 + tq * 2;
        *(uint32_t*)(g_Q + rA * 64 + col) = packbf(c[j][0] * invA, c[j][1] * invA);
        *(uint32_t*)(g_Q + (rA + 8) * 64 + col) = packbf(c[j][2] * invB, c[j][3] * invB);
    }
}

// ---------------- stage 3: attention (BM=128, split-K x2, cp.async pipeline) ----------------
#define CH 16
__global__ __launch_bounds__(256) void k_attn() {
    extern __shared__ __nv_bfloat16 dsm[];
    __nv_bfloat16* sQ = dsm;                 // 128*72
    __nv_bfloat16* sK0 = dsm + 9216;
    __nv_bfloat16* sV0 = dsm + 9216 * 2;
    __nv_bfloat16* sK1 = dsm + 9216 * 3;
    __nv_bfloat16* sV1 = dsm + 9216 * 4;
    int tid = threadIdx.x, lane = tid & 31, wid = tid >> 5;
    int b2 = blockIdx.y, tile = blockIdx.x, sp = blockIdx.z;
    const __nv_bfloat16* Qg = g_Q + (b2 * 4096 + tile * 128) * 64;
    const __nv_bfloat16* Kg = g_Q + b2 * 4096 * 64;
    const __nv_bfloat16* Vg = g_V + b2 * 4096 * 64;
    int gch0 = sp * CH;

    // G0: Q tile + chunk 0
    for (int i = tid; i < 1024; i += 256) {
        int row = i >> 3, c16 = i & 7;
        cp16(sptr(sQ + row * QPAD + c16 * 8), ((const uint4*)Qg) + i);
    }
    {
        const uint4* Ks = (const uint4*)(Kg + gch0 * 8192);
        const uint4* Vs = (const uint4*)(Vg + gch0 * 8192);
        for (int i = tid; i < 1024; i += 256) {
            int row = i >> 3, c16 = i & 7;
            cp16(sptr(sK0 + row * QPAD + c16 * 8), Ks + i);
            cp16(sptr(sV0 + row * QPAD + c16 * 8), Vs + i);
        }
    }
    cp_commit();
    // G1: chunk 1
    {
        const uint4* Ks = (const uint4*)(Kg + (gch0 + 1) * 8192);
        const uint4* Vs = (const uint4*)(Vg + (gch0 + 1) * 8192);
        for (int i = tid; i < 1024; i += 256) {
            int row = i >> 3, c16 = i & 7;
            cp16(sptr(sK1 + row * QPAD + c16 * 8), Ks + i);
            cp16(sptr(sV1 + row * QPAD + c16 * 8), Vs + i);
        }
    }
    cp_commit();
    asm volatile("cp.async.wait_group 1;");
    __syncthreads();

    int R0 = wid * 16;
    uint32_t aQ[4][4];
    {
        int qrow = R0 + (lane & 7) + ((lane >> 3) & 1) * 8;
        int qcol = ((lane >> 4) & 1) * 8;
#pragma unroll
        for (int s = 0; s < 4; s++) {
            uint32_t a = sptr(sQ + qrow * QPAD + s * 16 + qcol);
            ldsm_x4(a, aQ[s][0], aQ[s][1], aQ[s][2], aQ[s][3]);
        }
    }

    float o[8][4];
#pragma unroll
    for (int i = 0; i < 8; i++)
#pragma unroll
        for (int j = 0; j < 4; j++) o[i][j] = 0.f;
    float rs0 = 0.f, rs1 = 0.f;

    // K x4: lanes 0-15 -> block j8, lanes 16-31 -> block j8+1
    uint32_t laneK = ((lane & 7) * QPAD + ((lane >> 3) & 1) * 8 +
                      ((lane >> 4) & 1) * 8 * QPAD) * 2;
    // V x4t: lanes 0-15 -> rows of kk, lanes 16-31 -> rows of kk+1
    uint32_t laneV = (((lane & 7) + ((lane >> 3) & 1) * 8 + ((lane >> 4) & 1) * 16) * QPAD) * 2;
    uint32_t baseK[2] = {sptr(sK0), sptr(sK1)};
    uint32_t baseV[2] = {sptr(sV0), sptr(sV1)};

    for (int ch = 0; ch < CH; ch++) {
        uint32_t oKb = baseK[ch & 1] + laneK;
        uint32_t oVb = baseV[ch & 1] + laneV;

#pragma unroll
        for (int half = 0; half < 2; half++) {
            float c[8][4];
#pragma unroll
            for (int i = 0; i < 8; i++)
#pragma unroll
                for (int j = 0; j < 4; j++) c[i][j] = 0.f;
#pragma unroll
            for (int j8 = 0; j8 < 8; j8 += 2) {
                int j = half * 8 + j8;
#pragma unroll
                for (int s = 0; s < 4; s++) {
                    uint32_t b4[4];
                    ldsm_x4(oKb + (uint32_t)(j * 8 * QPAD + s * 16) * 2,
                            b4[0], b4[1], b4[2], b4[3]);
                    mma_bf16(c[j8], aQ[s], b4);
                    mma_bf16(c[j8 + 1], aQ[s], b4 + 2);
                }
            }
            uint32_t pf[4][4];
#pragma unroll
            for (int j8 = 0; j8 < 8; j8++) {
                float p0 = expp(c[j8][0]), p1 = expp(c[j8][1]);
                float p2 = expp(c[j8][2]), p3 = expp(c[j8][3]);
                rs0 += p0 + p1;
                rs1 += p2 + p3;
                int kk = j8 >> 1;
                int sub = (j8 & 1) * 2;
                pf[kk][sub + 0] = packbf(p0, p1);
                pf[kk][sub + 1] = packbf(p2, p3);
            }
#pragma unroll
            for (int n2 = 0; n2 < 8; n2++) {
#pragma unroll
                for (int kk = 0; kk < 4; kk += 2) {
                    uint32_t b4[4];
                    ldsm_x4t(oVb + (uint32_t)((half * 64 + kk * 16) * QPAD + n2 * 8) * 2,
                             b4[0], b4[1], b4[2], b4[3]);
                    mma_bf16(o[n2], pf[kk], b4);
                    mma_bf16(o[n2], pf[kk + 1], b4 + 2);
                }
            }
        }
        __syncthreads(); // everyone done reading buf[ch&1]
        if (ch + 2 < CH) {
            const uint4* Ks = (const uint4*)(Kg + (gch0 + ch + 2) * 8192);
            const uint4* Vs = (const uint4*)(Vg + (gch0 + ch + 2) * 8192);
            __nv_bfloat16* dK = (ch & 1) ? sK1 : sK0;
            __nv_bfloat16* dV = (ch & 1) ? sV1 : sV0;
            for (int i = tid; i < 1024; i += 256) {
                int row = i >> 3, c16 = i & 7;
                cp16(sptr(dK + row * QPAD + c16 * 8), Ks + i);
                cp16(sptr(dV + row * QPAD + c16 * 8), Vs + i);
            }
            cp_commit();
            asm volatile("cp.async.wait_group 1;");
        } else if (ch + 1 < CH) {
            asm volatile("cp.async.wait_group 0;");
        }
        __syncthreads();
    }

    rs0 += __shfl_xor_sync(0xffffffffu, rs0, 1);
    rs0 += __shfl_xor_sync(0xffffffffu, rs0, 2);
    rs1 += __shfl_xor_sync(0xffffffffu, rs1, 1);
    rs1 += __shfl_xor_sync(0xffffffffu, rs1, 2);
    int g = lane >> 2, tq = lane & 3;
    int row0 = b2 * 4096 + tile * 128 + R0 + g;
    float* O0 = g_Po + (size_t)sp * 1048576 + (size_t)row0 * 64;
#pragma unroll
    for (int n2 = 0; n2 < 8; n2++) {
        int col = n2 * 8 + tq * 2;
        *(float2*)(O0 + col) = make_float2(o[n2][0], o[n2][1]);
        *(float2*)(O0 + 8 * 64 + col) = make_float2(o[n2][2], o[n2][3]);
    }
    if (tq == 0) {
        g_Pd[sp * 16384 + row0] = rs0;
        g_Pd[sp * 16384 + row0 + 8] = rs1;
    }
}

// ---------------- stage 4: t = x + convl(concat(attn, unet)) + split combine ----------------
__global__ __launch_bounds__(256) void k_mix1(const float* __restrict__ x,
                                              const float* __restrict__ unet,
                                              const float* __restrict__ wl,
                                              const float* __restrict__ bl) {
    __shared__ float Rs[64 * 64];
    __shared__ float ws[64 * 65];
    __shared__ float us[64];
    __shared__ float bs[64];
    __shared__ float sd[64];
    int tid = threadIdx.x;
    int p0 = blockIdx.x * 64;
    int blk = blockIdx.x;
    for (int i = tid; i < 4160; i += 256) ws[i] = wl[i];
    if (tid < 64) {
        us[tid] = unet[p0 + tid];
        bs[tid] = bl[tid];
        int r = tid * 256 + blk;
        float d = g_Pd[r] + g_Pd[16384 + r];
        sd[tid] = 1.f / d;
    }
    __syncthreads();
    for (int k = 0; k < 16; k++) {
        int idx = k * 256 + tid;
        int c = idx >> 6;
        int f = c * HW + p0 + (idx & 63);
        float v = g_Po[f] + g_Po[f + 1048576];
        Rs[idx] = v * sd[c];
    }
    __syncthreads();
    int pp = tid & 63, cb = (tid >> 6) * 16;
    float uv = us[pp];
    float acc[16];
#pragma unroll
    for (int i = 0; i < 16; i++) acc[i] = bs[cb + i] + ws[(cb + i) * 65 + 64] * uv;
#pragma unroll 1
    for (int ci = 0; ci < 64; ci++) {
        float rv = Rs[ci * 64 + pp];
#pragma unroll
        for (int i = 0; i < 16; i++) acc[i] = fmaf(ws[(cb + i) * 65 + ci], rv, acc[i]);
    }
#pragma unroll
    for (int i = 0; i < 16; i++) {
        int off = (cb + i) * HW + p0 + pp;
        g_T[off] = x[off] + acc[i];
    }
}

// ---------------- stage 5/6: 3x3 convs (f32x2 packed FMA, relu) ----------------
template <int DIL, bool FIRST>
__global__ __launch_bounds__(256) void k_conv3f(const float* __restrict__ bias) {
    const float* in = FIRST ? g_T : g_Z1;
    float* out = FIRST ? g_Z1 : g_Z2;
    const float* wt = g_Wt[FIRST ? 0 : 1];
    const int TSW = 64 + 2 * DIL;
    __shared__ float ts[8][3][72];
    __shared__ __align__(16) float ws[8][9][64];
    int tid = threadIdx.x;
    int h = blockIdx.x;
    int wbase = blockIdx.y * 64;
    int wq = tid & 31;
    int cg = tid >> 5;
    unsigned long long acc[4][2];
#pragma unroll
    for (int j = 0; j < 4; j++)
#pragma unroll
        for (int k = 0; k < 2; k++) acc[j][k] = 0ull;

    for (int c0 = 0; c0 < 64; c0 += 8) {
        __syncthreads();
        for (int idx = tid; idx < 8 * 3 * TSW; idx += 256) {
            int ci = idx / (3 * TSW), rr = idx % (3 * TSW);
            int kr = rr / TSW, col = rr % TSW;
            int gw = wbase + col - DIL;
            int gh = h + (kr - 1) * DIL;
            float v = 0.f;
            if ((unsigned)gw < 128u && (unsigned)gh < 128u)
                v = in[(c0 + ci) * HW + gh * 128 + gw];
            ts[ci][kr][col] = v;
        }
        for (int idx = tid; idx < 4608; idx += 256)
            ((float*)ws)[idx] = wt[c0 * 576 + idx];
        __syncthreads();
#pragma unroll
        for (int ci = 0; ci < 8; ci++) {
#pragma unroll
            for (int kr = 0; kr < 3; kr++)
#pragma unroll
                for (int kc = 0; kc < 3; kc++) {
                    unsigned long long t2[2];
#pragma unroll
                    for (int k = 0; k < 2; k++)
                        t2[k] = dupf(ts[ci][kr][wq + 32 * k + kc * DIL]);
#pragma unroll
                    for (int j = 0; j < 4; j++) {
                        unsigned long long w2 =
                            *(const unsigned long long*)&ws[ci][kr * 3 + kc][cg * 8 + j * 2];
#pragma unroll
                        for (int k = 0; k < 2; k++) fma2(acc[j][k], t2[k], w2);
                    }
                }
        }
    }
#pragma unroll
    for (int j = 0; j < 4; j++) {
        int co = cg * 8 + j * 2;
        float b0 = bias[co], b1 = bias[co + 1];
#pragma unroll
        for (int k = 0; k < 2; k++) {
            float lo, hi;
            unpackf(acc[j][k], lo, hi);
            out[co * HW + h * 128 + wbase + wq + 32 * k] = fmaxf(lo + b0, 0.f);
            out[(co + 1) * HW + h * 128 + wbase + wq + 32 * k] = fmaxf(hi + b1, 0.f);
        }
    }
}

// ---------------- stage 7: out = x + conv1x1(z2) ----------------
__global__ __launch_bounds__(256) void k_mix2(const float* __restrict__ x,
                                              const float* __restrict__ w3,
                                              const float* __restrict__ b3,
                                              float* __restrict__ out) {
    __shared__ float Rs[64 * 64];
    __shared__ float ws[64 * 64];
    __shared__ float bs[64];
    int tid = threadIdx.x;
    int p0 = blockIdx.x * 64;
    for (int i = tid; i < 4096; i += 256) ws[i] = w3[i];
    if (tid < 64) bs[tid] = b3[tid];
    for (int k = 0; k < 16; k++) {
        int idx = k * 256 + tid;
        Rs[idx] = g_Z2[(idx >> 6) * HW + p0 + (idx & 63)];
    }
    __syncthreads();
    int pp = tid & 63, cb = (tid >> 6) * 16;
    float acc[16];
#pragma unroll
    for (int i = 0; i < 16; i++) acc[i] = bs[cb + i];
#pragma unroll 1
    for (int ci = 0; ci < 64; ci++) {
        float rv = Rs[ci * 64 + pp];
#pragma unroll
        for (int i = 0; i < 16; i++) acc[i] = fmaf(ws[(cb + i) * 64 + ci], rv, acc[i]);
    }
#pragma unroll
    for (int i = 0; i < 16; i++) {
        int off = (cb + i) * HW + p0 + pp;
        out[off] = x[off] + acc[i];
    }
}

// ---------------- launcher ----------------
extern "C" void kernel_launch(void* const* d_in, const int* in_sizes, int n_in,
                              void* d_out, int out_size) {
    (void)in_sizes; (void)n_in; (void)out_size;
    const float* x    = (const float*)d_in[0];
    const float* unet = (const float*)d_in[1];
    const float* wqk  = (const float*)d_in[2];
    const float* w1   = (const float*)d_in[3];
    const float* b1   = (const float*)d_in[4];
    const float* w2   = (const float*)d_in[5];
    const float* b2   = (const float*)d_in[6];
    const float* w3   = (const float*)d_in[7];
    const float* b3   = (const float*)d_in[8];
    const float* wl   = (const float*)d_in[9];
    const float* bl   = (const float*)d_in[10];
    float* out = (float*)d_out;

    const int ATTN_SMEM = 9216 * 5 * 2; // 92160 bytes
    cudaFuncSetAttribute(k_attn, cudaFuncAttributeMaxDynamicSharedMemorySize, ATTN_SMEM);

    k_red1<<<1024, 256>>>((const float4*)x);
    k_red2<<<1, 1024>>>(wqk);
    k_wprep<<<dim3(144, 2), 256>>>(w1, w2);
    k_build<<<256, 128>>>(x, wqk);
    k_attn<<<dim3(32, 4, 2), 256, ATTN_SMEM>>>();
    k_mix1<<<256, 256>>>(x, unet, wl, bl);
    k_conv3f<1, true><<<dim3(128, 2), 256>>>(b1);
    k_conv3f<2, false><<<dim3(128, 2), 256>>>(b2);
    k_mix2<<<256, 256>>>(x, w3, b3, out);
}

// round 8
// speedup vs baseline: 1.0084x; 1.0084x over previous
#include <cuda_runtime.h>
#include <cuda_bf16.h>
#include <stdint.h>

#define HW 16384
#define NPIX 1048576
#define QPAD 72

// ---------------- scratch (static device allocations) ----------------
__device__ float g_part[2048];
__device__ float g_stats[2];                 // mean
__device__ float g_csum[64];                 // colsum(wqk)
__device__ __nv_bfloat16 g_Q[4 * 4096 * 64]; // unit-norm q * (1/sqrt(8)) (bf16)
__device__ __nv_bfloat16 g_V[4 * 4096 * 64]; // raw v (bf16)
__device__ float g_Po[2 * 16384 * 64];       // split-K partial attn out
__device__ float g_Pd[2 * 16384];            // split-K partial denominators
__device__ float g_T[64 * HW];               // x + convl(...)
__device__ float g_Z1[64 * HW];
__device__ float g_Z2[64 * HW];
__device__ float g_Wt[2][64 * 9 * 64];       // transposed conv weights [(cin*9+kk)*64+co]

// ---------------- f32x2 / misc helpers ----------------
__device__ __forceinline__ unsigned long long dupf(float v) {
    unsigned long long r;
    uint32_t b = __float_as_uint(v);
    asm("mov.b64 %0, {%1,%1};" : "=l"(r) : "r"(b));
    return r;
}
__device__ __forceinline__ void unpackf(unsigned long long v, float& lo, float& hi) {
    uint32_t a, b;
    asm("mov.b64 {%0,%1}, %2;" : "=r"(a), "=r"(b) : "l"(v));
    lo = __uint_as_float(a);
    hi = __uint_as_float(b);
}
__device__ __forceinline__ void fma2(unsigned long long& d, unsigned long long a,
                                     unsigned long long b) {
    asm("fma.rn.f32x2 %0, %1, %2, %0;" : "+l"(d) : "l"(a), "l"(b));
}
__device__ __forceinline__ uint32_t packbf(float lo, float hi) {
    uint32_t r;
    asm("cvt.rn.bf16x2.f32 %0, %1, %2;" : "=r"(r) : "f"(hi), "f"(lo));
    return r;
}
__device__ __forceinline__ uint32_t sptr(const void* p) {
    return (uint32_t)__cvta_generic_to_shared(p);
}
__device__ __forceinline__ void cp16(uint32_t dst, const void* src) {
    asm volatile("cp.async.cg.shared.global [%0], [%1], 16;" :: "r"(dst), "l"(src));
}
__device__ __forceinline__ void cp_commit() {
    asm volatile("cp.async.commit_group;");
}
__device__ __forceinline__ void ldsm_x4(uint32_t a, uint32_t& r0, uint32_t& r1,
                                        uint32_t& r2, uint32_t& r3) {
    asm volatile("ldmatrix.sync.aligned.m8n8.x4.shared.b16 {%0,%1,%2,%3},[%4];"
                 : "=r"(r0), "=r"(r1), "=r"(r2), "=r"(r3) : "r"(a));
}
__device__ __forceinline__ void ldsm_x4t(uint32_t a, uint32_t& r0, uint32_t& r1,
                                         uint32_t& r2, uint32_t& r3) {
    asm volatile("ldmatrix.sync.aligned.m8n8.x4.trans.shared.b16 {%0,%1,%2,%3},[%4];"
                 : "=r"(r0), "=r"(r1), "=r"(r2), "=r"(r3) : "r"(a));
}
__device__ __forceinline__ void ldsm_x2(uint32_t a, uint32_t& r0, uint32_t& r1) {
    asm volatile("ldmatrix.sync.aligned.m8n8.x2.shared.b16 {%0,%1},[%2];"
                 : "=r"(r0), "=r"(r1) : "r"(a));
}
__device__ __forceinline__ void mma_bf16(float* d, const uint32_t* a, const uint32_t* b) {
    asm volatile(
        "mma.sync.aligned.m16n8k16.row.col.f32.bf16.bf16.f32 "
        "{%0,%1,%2,%3},{%4,%5,%6,%7},{%8,%9},{%0,%1,%2,%3};"
        : "+f"(d[0]), "+f"(d[1]), "+f"(d[2]), "+f"(d[3])
        : "r"(a[0]), "r"(a[1]), "r"(a[2]), "r"(a[3]), "r"(b[0]), "r"(b[1]));
}
// exp(d), |d| <= ~0.13 (deg-4 Taylor)
__device__ __forceinline__ float expp(float d) {
    return fmaf(d, fmaf(d, fmaf(d, fmaf(d, 0.041666668f, 0.16666667f), 0.5f), 1.f), 1.f);
}

// ---------------- stage 1: mean over all of x ----------------
__global__ void k_red1(const float4* __restrict__ x4) {
    int i = blockIdx.x * 256 + threadIdx.x;
    float4 v = x4[i];
    float s = v.x + v.y + v.z + v.w;
    for (int o = 16; o; o >>= 1) s += __shfl_xor_sync(0xffffffffu, s, o);
    __shared__ float sh[8];
    int w = threadIdx.x >> 5, l = threadIdx.x & 31;
    if (l == 0) sh[w] = s;
    __syncthreads();
    if (threadIdx.x == 0) {
        float S = 0;
        for (int k = 0; k < 8; k++) S += sh[k];
        g_part[blockIdx.x] = S;
    }
}

__global__ void k_red2(const float* __restrict__ wqk) {
    int tid = threadIdx.x; // 1024 threads
    // colsum(wqk) once for the whole grid (threads 0..63)
    if (tid < 64) {
        float s = 0.f;
#pragma unroll
        for (int c = 0; c < 64; c++) s += wqk[c * 64 + tid];
        g_csum[tid] = s;
    }
    float s = g_part[tid];
    for (int o = 16; o; o >>= 1) s += __shfl_xor_sync(0xffffffffu, s, o);
    __shared__ float sh[32];
    int w = tid >> 5, l = tid & 31;
    if (l == 0) sh[w] = s;
    __syncthreads();
    if (tid == 0) {
        float S = 0;
        for (int k = 0; k < 32; k++) S += sh[k];
        g_stats[0] = S / (float)NPIX;
    }
}

// ---------------- weight transpose for conv smem coalescing ----------------
__global__ void k_wprep(const float* __restrict__ w1, const float* __restrict__ w2) {
    int i = blockIdx.x * 256 + threadIdx.x; // 36864 per conv
    const float* src = blockIdx.y ? w2 : w1;
    int co = i & 63, r = i >> 6;
    int krkc = r % 9, cin = r / 9;
    g_Wt[blockIdx.y][i] = src[(co * 64 + cin) * 9 + krkc];
}

// ---------------- stage 2: build Q (tensor-core) and V ----------------
// q_row = normalize( x_row @ W  -  mean * colsum(W) ) * (1/sqrt 8)
__global__ __launch_bounds__(128) void k_build(const float* __restrict__ x,
                                               const float* __restrict__ wqk) {
    __shared__ __nv_bfloat16 sW[64 * QPAD]; // W^T: sW[e][c]
    __shared__ __nv_bfloat16 sX[64 * QPAD]; // sX[i][c]
    __shared__ float scs[64];
    int tid = threadIdx.x, lane = tid & 31, wid = tid >> 5;
    int r0 = blockIdx.x * 64;
    int b2 = r0 >> 12;
    int hrow = (((r0 & 4095) >> 6) << 1) + (b2 >> 1);
    int wofs = b2 & 1;
    const float* xb = x + hrow * 128 + wofs;

    for (int idx = tid; idx < 4096; idx += 128) {
        int c = idx >> 6, e = idx & 63;
        sW[e * QPAD + c] = __float2bfloat16(wqk[idx]);
    }
    for (int idx = tid; idx < 4096; idx += 128) {
        int c = idx >> 6, i = idx & 63;
        sX[i * QPAD + c] = __float2bfloat16(xb[c * HW + 2 * i]);
    }
    if (tid < 64) scs[tid] = g_csum[tid];
    __syncthreads();

    // write V (raw bf16 x)
    for (int i2 = tid; i2 < 512; i2 += 128) {
        int i = i2 >> 3, c16 = i2 & 7;
        *(uint4*)(g_V + (r0 + i) * 64 + c16 * 8) = *(const uint4*)(sX + i * QPAD + c16 * 8);
    }

    int R0 = wid * 16;
    uint32_t aX[4][4];
    {
        int qrow = R0 + (lane & 7) + ((lane >> 3) & 1) * 8;
        int qcol = ((lane >> 4) & 1) * 8;
#pragma unroll
        for (int s = 0; s < 4; s++) {
            uint32_t a = sptr(sX + qrow * QPAD + s * 16 + qcol);
            ldsm_x4(a, aX[s][0], aX[s][1], aX[s][2], aX[s][3]);
        }
    }
    uint32_t offB = sptr(sW) + ((lane & 7) * QPAD + ((lane >> 3) & 1) * 8) * 2;

    float c[8][4];
#pragma unroll
    for (int j = 0; j < 8; j++)
#pragma unroll
        for (int t = 0; t < 4; t++) c[j][t] = 0.f;
#pragma unroll
    for (int j = 0; j < 8; j++)
#pragma unroll
        for (int s = 0; s < 4; s++) {
            uint32_t b[2];
            ldsm_x2(offB + (uint32_t)(j * 8 * QPAD + s * 16) * 2, b[0], b[1]);
            mma_bf16(c[j], aX[s], b);
        }

    float nmean = -g_stats[0];
    int g = lane >> 2, tq = lane & 3;
    float ssA = 0.f, ssB = 0.f;
#pragma unroll
    for (int j = 0; j < 8; j++) {
        float b0 = nmean * scs[j * 8 + tq * 2];
        float b1 = nmean * scs[j * 8 + tq * 2 + 1];
        c[j][0] += b0; c[j][1] += b1; c[j][2] += b0; c[j][3] += b1;
        ssA += c[j][0] * c[j][0] + c[j][1] * c[j][1];
        ssB += c[j][2] * c[j][2] + c[j][3] * c[j][3];
    }
    ssA += __shfl_xor_sync(0xffffffffu, ssA, 1);
    ssA += __shfl_xor_sync(0xffffffffu, ssA, 2);
    ssB += __shfl_xor_sync(0xffffffffu, ssB, 1);
    ssB += __shfl_xor_sync(0xffffffffu, ssB, 2);
    const float S8 = 0.35355339059327373f; // 1/sqrt(8)
    float invA = S8 / (sqrtf(ssA) + 1e-8f);
    float invB = S8 / (sqrtf(ssB) + 1e-8f);

    int rA = r0 + R0 + g;
#pragma unroll
    for (int j = 0; j < 8; j++) {
        int col = j * 8 + tq * 2;
        *(uint32_t*)(g_Q + rA * 64 + col) = packbf(c[j][0] * invA, c[j][1] * invA);
        *(uint32_t*)(g_Q + (rA + 8) * 64 + col) = packbf(c[j][2] * invB, c[j][3] * invB);
    }
}

// ---------------- stage 3: attention (BM=128, split-K x2, cp.async pipeline) ----------------
#define CH 16
__global__ __launch_bounds__(256) void k_attn() {
    extern __shared__ __nv_bfloat16 dsm[];
    __nv_bfloat16* sQ = dsm;                 // 128*72
    __nv_bfloat16* sK0 = dsm + 9216;
    __nv_bfloat16* sV0 = dsm + 9216 * 2;
    __nv_bfloat16* sK1 = dsm + 9216 * 3;
    __nv_bfloat16* sV1 = dsm + 9216 * 4;
    int tid = threadIdx.x, lane = tid & 31, wid = tid >> 5;
    int b2 = blockIdx.y, tile = blockIdx.x, sp = blockIdx.z;
    const __nv_bfloat16* Qg = g_Q + (b2 * 4096 + tile * 128) * 64;
    const __nv_bfloat16* Kg = g_Q + b2 * 4096 * 64;
    const __nv_bfloat16* Vg = g_V + b2 * 4096 * 64;
    int gch0 = sp * CH;

    // G0: Q tile + chunk 0
    for (int i = tid; i < 1024; i += 256) {
        int row = i >> 3, c16 = i & 7;
        cp16(sptr(sQ + row * QPAD + c16 * 8), ((const uint4*)Qg) + i);
    }
    {
        const uint4* Ks = (const uint4*)(Kg + gch0 * 8192);
        const uint4* Vs = (const uint4*)(Vg + gch0 * 8192);
        for (int i = tid; i < 1024; i += 256) {
            int row = i >> 3, c16 = i & 7;
            cp16(sptr(sK0 + row * QPAD + c16 * 8), Ks + i);
            cp16(sptr(sV0 + row * QPAD + c16 * 8), Vs + i);
        }
    }
    cp_commit();
    // G1: chunk 1
    {
        const uint4* Ks = (const uint4*)(Kg + (gch0 + 1) * 8192);
        const uint4* Vs = (const uint4*)(Vg + (gch0 + 1) * 8192);
        for (int i = tid; i < 1024; i += 256) {
            int row = i >> 3, c16 = i & 7;
            cp16(sptr(sK1 + row * QPAD + c16 * 8), Ks + i);
            cp16(sptr(sV1 + row * QPAD + c16 * 8), Vs + i);
        }
    }
    cp_commit();
    asm volatile("cp.async.wait_group 1;");
    __syncthreads();

    int R0 = wid * 16;
    uint32_t aQ[4][4];
    {
        int qrow = R0 + (lane & 7) + ((lane >> 3) & 1) * 8;
        int qcol = ((lane >> 4) & 1) * 8;
#pragma unroll
        for (int s = 0; s < 4; s++) {
            uint32_t a = sptr(sQ + qrow * QPAD + s * 16 + qcol);
            ldsm_x4(a, aQ[s][0], aQ[s][1], aQ[s][2], aQ[s][3]);
        }
    }

    float o[8][4];
#pragma unroll
    for (int i = 0; i < 8; i++)
#pragma unroll
        for (int j = 0; j < 4; j++) o[i][j] = 0.f;
    float rs0 = 0.f, rs1 = 0.f;

    // K x4: lanes 0-15 -> block j8, lanes 16-31 -> block j8+1
    uint32_t laneK = ((lane & 7) * QPAD + ((lane >> 3) & 1) * 8 +
                      ((lane >> 4) & 1) * 8 * QPAD) * 2;
    // V x4t: lanes 0-15 -> rows of kk, lanes 16-31 -> rows of kk+1
    uint32_t laneV = (((lane & 7) + ((lane >> 3) & 1) * 8 + ((lane >> 4) & 1) * 16) * QPAD) * 2;
    uint32_t baseK[2] = {sptr(sK0), sptr(sK1)};
    uint32_t baseV[2] = {sptr(sV0), sptr(sV1)};

    for (int ch = 0; ch < CH; ch++) {
        uint32_t oKb = baseK[ch & 1] + laneK;
        uint32_t oVb = baseV[ch & 1] + laneV;

#pragma unroll
        for (int half = 0; half < 2; half++) {
            float c[8][4];
#pragma unroll
            for (int i = 0; i < 8; i++)
#pragma unroll
                for (int j = 0; j < 4; j++) c[i][j] = 0.f;
#pragma unroll
            for (int j8 = 0; j8 < 8; j8 += 2) {
                int j = half * 8 + j8;
#pragma unroll
                for (int s = 0; s < 4; s++) {
                    uint32_t b4[4];
                    ldsm_x4(oKb + (uint32_t)(j * 8 * QPAD + s * 16) * 2,
                            b4[0], b4[1], b4[2], b4[3]);
                    mma_bf16(c[j8], aQ[s], b4);
                    mma_bf16(c[j8 + 1], aQ[s], b4 + 2);
                }
            }
            uint32_t pf[4][4];
#pragma unroll
            for (int j8 = 0; j8 < 8; j8++) {
                float p0 = expp(c[j8][0]), p1 = expp(c[j8][1]);
                float p2 = expp(c[j8][2]), p3 = expp(c[j8][3]);
                rs0 += p0 + p1;
                rs1 += p2 + p3;
                int kk = j8 >> 1;
                int sub = (j8 & 1) * 2;
                pf[kk][sub + 0] = packbf(p0, p1);
                pf[kk][sub + 1] = packbf(p2, p3);
            }
#pragma unroll
            for (int n2 = 0; n2 < 8; n2++) {
#pragma unroll
                for (int kk = 0; kk < 4; kk += 2) {
                    uint32_t b4[4];
                    ldsm_x4t(oVb + (uint32_t)((half * 64 + kk * 16) * QPAD + n2 * 8) * 2,
                             b4[0], b4[1], b4[2], b4[3]);
                    mma_bf16(o[n2], pf[kk], b4);
                    mma_bf16(o[n2], pf[kk + 1], b4 + 2);
                }
            }
        }
        __syncthreads(); // everyone done reading buf[ch&1]
        if (ch + 2 < CH) {
            const uint4* Ks = (const uint4*)(Kg + (gch0 + ch + 2) * 8192);
            const uint4* Vs = (const uint4*)(Vg + (gch0 + ch + 2) * 8192);
            __nv_bfloat16* dK = (ch & 1) ? sK1 : sK0;
            __nv_bfloat16* dV = (ch & 1) ? sV1 : sV0;
            for (int i = tid; i < 1024; i += 256) {
                int row = i >> 3, c16 = i & 7;
                cp16(sptr(dK + row * QPAD + c16 * 8), Ks + i);
                cp16(sptr(dV + row * QPAD + c16 * 8), Vs + i);
            }
            cp_commit();
            asm volatile("cp.async.wait_group 1;");
        } else if (ch + 1 < CH) {
            asm volatile("cp.async.wait_group 0;");
        }
        __syncthreads();
    }

    rs0 += __shfl_xor_sync(0xffffffffu, rs0, 1);
    rs0 += __shfl_xor_sync(0xffffffffu, rs0, 2);
    rs1 += __shfl_xor_sync(0xffffffffu, rs1, 1);
    rs1 += __shfl_xor_sync(0xffffffffu, rs1, 2);
    int g = lane >> 2, tq = lane & 3;
    int row0 = b2 * 4096 + tile * 128 + R0 + g;
    float* O0 = g_Po + (size_t)sp * 1048576 + (size_t)row0 * 64;
#pragma unroll
    for (int n2 = 0; n2 < 8; n2++) {
        int col = n2 * 8 + tq * 2;
        *(float2*)(O0 + col) = make_float2(o[n2][0], o[n2][1]);
        *(float2*)(O0 + 8 * 64 + col) = make_float2(o[n2][2], o[n2][3]);
    }
    if (tq == 0) {
        g_Pd[sp * 16384 + row0] = rs0;
        g_Pd[sp * 16384 + row0 + 8] = rs1;
    }
}

// ---------------- stage 4: t = x + convl(concat(attn, unet)) + split combine ----------------
__global__ __launch_bounds__(256) void k_mix1(const float* __restrict__ x,
                                              const float* __restrict__ unet,
                                              const float* __restrict__ wl,
                                              const float* __restrict__ bl) {
    __shared__ float Rs[64 * 64];
    __shared__ float ws[64 * 65];
    __shared__ float us[64];
    __shared__ float bs[64];
    __shared__ float sd[64];
    int tid = threadIdx.x;
    int p0 = blockIdx.x * 64;
    int blk = blockIdx.x;
    for (int i = tid; i < 4160; i += 256) ws[i] = wl[i];
    if (tid < 64) {
        us[tid] = unet[p0 + tid];
        bs[tid] = bl[tid];
        int r = tid * 256 + blk;
        float d = g_Pd[r] + g_Pd[16384 + r];
        sd[tid] = 1.f / d;
    }
    __syncthreads();
    for (int k = 0; k < 16; k++) {
        int idx = k * 256 + tid;
        int c = idx >> 6;
        int f = c * HW + p0 + (idx & 63);
        float v = g_Po[f] + g_Po[f + 1048576];
        Rs[idx] = v * sd[c];
    }
    __syncthreads();
    int pp = tid & 63, cb = (tid >> 6) * 16;
    float uv = us[pp];
    float acc[16];
#pragma unroll
    for (int i = 0; i < 16; i++) acc[i] = bs[cb + i] + ws[(cb + i) * 65 + 64] * uv;
#pragma unroll 1
    for (int ci = 0; ci < 64; ci++) {
        float rv = Rs[ci * 64 + pp];
#pragma unroll
        for (int i = 0; i < 16; i++) acc[i] = fmaf(ws[(cb + i) * 65 + ci], rv, acc[i]);
    }
#pragma unroll
    for (int i = 0; i < 16; i++) {
        int off = (cb + i) * HW + p0 + pp;
        g_T[off] = x[off] + acc[i];
    }
}

// ---------------- stage 5/6: 3x3 convs (f32x2 packed FMA, relu) ----------------
template <int DIL, bool FIRST>
__global__ __launch_bounds__(256) void k_conv3f(const float* __restrict__ bias) {
    const float* in = FIRST ? g_T : g_Z1;
    float* out = FIRST ? g_Z1 : g_Z2;
    const float* wt = g_Wt[FIRST ? 0 : 1];
    const int TSW = 64 + 2 * DIL;
    __shared__ float ts[8][3][72];
    __shared__ __align__(16) float ws[8][9][64];
    int tid = threadIdx.x;
    int h = blockIdx.x;
    int wbase = blockIdx.y * 64;
    int wq = tid & 31;
    int cg = tid >> 5;
    unsigned long long acc[4][2];
#pragma unroll
    for (int j = 0; j < 4; j++)
#pragma unroll
        for (int k = 0; k < 2; k++) acc[j][k] = 0ull;

    for (int c0 = 0; c0 < 64; c0 += 8) {
        __syncthreads();
        for (int idx = tid; idx < 8 * 3 * TSW; idx += 256) {
            int ci = idx / (3 * TSW), rr = idx % (3 * TSW);
            int kr = rr / TSW, col = rr % TSW;
            int gw = wbase + col - DIL;
            int gh = h + (kr - 1) * DIL;
            float v = 0.f;
            if ((unsigned)gw < 128u && (unsigned)gh < 128u)
                v = in[(c0 + ci) * HW + gh * 128 + gw];
            ts[ci][kr][col] = v;
        }
        for (int idx = tid; idx < 4608; idx += 256)
            ((float*)ws)[idx] = wt[c0 * 576 + idx];
        __syncthreads();
#pragma unroll
        for (int ci = 0; ci < 8; ci++) {
#pragma unroll
            for (int kr = 0; kr < 3; kr++)
#pragma unroll
                for (int kc = 0; kc < 3; kc++) {
                    unsigned long long t2[2];
#pragma unroll
                    for (int k = 0; k < 2; k++)
                        t2[k] = dupf(ts[ci][kr][wq + 32 * k + kc * DIL]);
#pragma unroll
                    for (int j = 0; j < 4; j++) {
                        unsigned long long w2 =
                            *(const unsigned long long*)&ws[ci][kr * 3 + kc][cg * 8 + j * 2];
#pragma unroll
                        for (int k = 0; k < 2; k++) fma2(acc[j][k], t2[k], w2);
                    }
                }
        }
    }
#pragma unroll
    for (int j = 0; j < 4; j++) {
        int co = cg * 8 + j * 2;
        float b0 = bias[co], b1 = bias[co + 1];
#pragma unroll
        for (int k = 0; k < 2; k++) {
            float lo, hi;
            unpackf(acc[j][k], lo, hi);
            out[co * HW + h * 128 + wbase + wq + 32 * k] = fmaxf(lo + b0, 0.f);
            out[(co + 1) * HW + h * 128 + wbase + wq + 32 * k] = fmaxf(hi + b1, 0.f);
        }
    }
}

// ---------------- stage 7: out = x + conv1x1(z2) ----------------
__global__ __launch_bounds__(256) void k_mix2(const float* __restrict__ x,
                                              const float* __restrict__ w3,
                                              const float* __restrict__ b3,
                                              float* __restrict__ out) {
    __shared__ float Rs[64 * 64];
    __shared__ float ws[64 * 64];
    __shared__ float bs[64];
    int tid = threadIdx.x;
    int p0 = blockIdx.x * 64;
    for (int i = tid; i < 4096; i += 256) ws[i] = w3[i];
    if (tid < 64) bs[tid] = b3[tid];
    for (int k = 0; k < 16; k++) {
        int idx = k * 256 + tid;
        Rs[idx] = g_Z2[(idx >> 6) * HW + p0 + (idx & 63)];
    }
    __syncthreads();
    int pp = tid & 63, cb = (tid >> 6) * 16;
    float acc[16];
#pragma unroll
    for (int i = 0; i < 16; i++) acc[i] = bs[cb + i];
#pragma unroll 1
    for (int ci = 0; ci < 64; ci++) {
        float rv = Rs[ci * 64 + pp];
#pragma unroll
        for (int i = 0; i < 16; i++) acc[i] = fmaf(ws[(cb + i) * 64 + ci], rv, acc[i]);
    }
#pragma unroll
    for (int i = 0; i < 16; i++) {
        int off = (cb + i) * HW + p0 + pp;
        out[off] = x[off] + acc[i];
    }
}

// ---------------- launcher ----------------
extern "C" void kernel_launch(void* const* d_in, const int* in_sizes, int n_in,
                              void* d_out, int out_size) {
    (void)in_sizes; (void)n_in; (void)out_size;
    const float* x    = (const float*)d_in[0];
    const float* unet = (const float*)d_in[1];
    const float* wqk  = (const float*)d_in[2];
    const float* w1   = (const float*)d_in[3];
    const float* b1   = (const float*)d_in[4];
    const float* w2   = (const float*)d_in[5];
    const float* b2   = (const float*)d_in[6];
    const float* w3   = (const float*)d_in[7];
    const float* b3   = (const float*)d_in[8];
    const float* wl   = (const float*)d_in[9];
    const float* bl   = (const float*)d_in[10];
    float* out = (float*)d_out;

    const int ATTN_SMEM = 9216 * 5 * 2; // 92160 bytes
    cudaFuncSetAttribute(k_attn, cudaFuncAttributeMaxDynamicSharedMemorySize, ATTN_SMEM);

    k_red1<<<1024, 256>>>((const float4*)x);
    k_red2<<<1, 1024>>>(wqk);
    k_wprep<<<dim3(144, 2), 256>>>(w1, w2);
    k_build<<<256, 128>>>(x, wqk);
    k_attn<<<dim3(32, 4, 2), 256, ATTN_SMEM>>>();
    k_mix1<<<256, 256>>>(x, unet, wl, bl);
    k_conv3f<1, true><<<dim3(128, 2), 256>>>(b1);
    k_conv3f<2, false><<<dim3(128, 2), 256>>>(b2);
    k_mix2<<<256, 256>>>(x, w3, b3, out);
}